// round 13
// baseline (speedup 1.0000x reference)
#include <cuda_runtime.h>

#define BATCH   64
#define NPTS    4096
#define CHUNKS  4
#define NFRAMES 100
#define FSPLIT  3            // frame ranges 34/33/33 -> GRID=768 ~= one balanced wave
#define FMAX    34
#define TPB     256
#define KPT     4            // NPTS / (CHUNKS*TPB)
#define GRID    (BATCH * CHUNKS * FSPLIT)

__device__ double g_sum;
__device__ double g_msum;
__device__ unsigned int g_count;

__device__ __forceinline__ float sqrt_approx(float x) {
    float r;
    asm("sqrt.approx.f32 %0, %1;" : "=f"(r) : "f"(x));
    return r;
}
// Last FFMA of the dot-chain carries .sat: clamps s' to [0,1].
// With e' = 0.1*e, saturate(s') == clamp(d^2,0,100)/100, so
// sqrt(sat) == min(d,10)/10 exactly (clamp + loss-unit fused, zero alu ops).
__device__ __forceinline__ float fma_sat(float a, float b, float c) {
    float r;
    asm("fma.rn.sat.f32 %0, %1, %2, %3;" : "=f"(r) : "f"(a), "f"(b), "f"(c));
    return r;
}

__global__ void __launch_bounds__(TPB) fape_kernel(
    const float* __restrict__ pred, const float* __restrict__ tru,
    const float* __restrict__ mask, float* __restrict__ out)
{
    // Frame constants (prescaled by 0.1) for this CTA's frame slice:
    //   sf[f] = (-2*e'_fx, -2*e'_fy, -2*e'_fz, ||e'_f||^2)
    __shared__ float4 sf[FMAX];
    __shared__ float wsum[TPB / 32], wm[TPB / 32];

    const int b     = blockIdx.x / (CHUNKS * FSPLIT);
    const int rem   = blockIdx.x % (CHUNKS * FSPLIT);
    const int chunk = rem / FSPLIT;
    const int fh    = rem % FSPLIT;
    const int tid   = threadIdx.x;

    // frame range: fh0 [0,34), fh1 [34,67), fh2 [67,100)
    const int fstart = (fh == 0) ? 0 : (fh == 1 ? 34 : 67);
    const int fcnt   = (fh == 0) ? 34 : 33;

    const float* pb = pred + (size_t)b * NPTS * 3;
    const float* tb = tru  + (size_t)b * NPTS * 3;
    const float* mb = mask + (size_t)b * NPTS;

    if (tid < fcnt) {
        int f = fstart + tid;
        float ex = 0.1f * (pb[3 * f + 0] - tb[3 * f + 0]);
        float ey = 0.1f * (pb[3 * f + 1] - tb[3 * f + 1]);
        float ez = 0.1f * (pb[3 * f + 2] - tb[3 * f + 2]);
        float nf = fmaf(ex, ex, fmaf(ey, ey, ez * ez));
        sf[tid] = make_float4(-2.f * ex, -2.f * ey, -2.f * ez, nf);
    }
    __syncthreads();

    // Four k-points per thread (independent chains -> ILP), prescaled by 0.1
    const int kbase = chunk * (TPB * KPT) + tid;
    float ex[KPT], ey[KPT], ez[KPT], nn[KPT], acc[KPT];
#pragma unroll
    for (int j = 0; j < KPT; ++j) {
        int k = kbase + j * TPB;
        ex[j] = 0.1f * (pb[3 * k + 0] - tb[3 * k + 0]);
        ey[j] = 0.1f * (pb[3 * k + 1] - tb[3 * k + 1]);
        ez[j] = 0.1f * (pb[3 * k + 2] - tb[3 * k + 2]);
        nn[j] = fmaf(ex[j], ex[j], fmaf(ey[j], ey[j], ez[j] * ez[j]));
        acc[j] = 0.f;
    }

#pragma unroll 4
    for (int f = 0; f < fcnt; ++f) {
        float4 F = sf[f];
#pragma unroll
        for (int j = 0; j < KPT; ++j) {
            // s' = sat( n'_k + n'_f + e'_k . (-2 e'_f) ) in [0,1]
            float s = fma_sat(ex[j], F.x,
                              fmaf(ey[j], F.y,
                                   fmaf(ez[j], F.z, nn[j] + F.w)));
            acc[j] += sqrt_approx(s);   // == min(d,10)/10
        }
    }

    float tsum = 0.f, msum = 0.f;
#pragma unroll
    for (int j = 0; j < KPT; ++j) {
        float m = mb[kbase + j * TPB];
        tsum = fmaf(m, acc[j], tsum);
        msum += m;
    }
    // mask sum counted once (frame-split duplicates k-coverage): only fh==0 counts
    if (fh != 0) msum = 0.f;

    // warp reduce
#pragma unroll
    for (int off = 16; off; off >>= 1) {
        tsum += __shfl_down_sync(0xffffffffu, tsum, off);
        msum += __shfl_down_sync(0xffffffffu, msum, off);
    }
    int wid = tid >> 5, lane = tid & 31;
    if (lane == 0) { wsum[wid] = tsum; wm[wid] = msum; }
    __syncthreads();

    if (wid == 0 && lane == 0) {
        float ts = 0.f, ms = 0.f;
#pragma unroll
        for (int w = 0; w < TPB / 32; ++w) { ts += wsum[w]; ms += wm[w]; }
        atomicAdd(&g_sum, (double)ts);
        atomicAdd(&g_msum, (double)ms);
        __threadfence();
        unsigned int done = atomicAdd(&g_count, 1u);
        if (done == GRID - 1) {
            // last CTA: finalize and reset scratch for next graph replay
            // per-pair terms already include the /10 loss unit (prescale form)
            double s = atomicAdd(&g_sum, 0.0);
            double m = atomicAdd(&g_msum, 0.0);
            out[0] = (float)(s / (m + 1e-8));
            g_sum = 0.0;
            g_msum = 0.0;
            g_count = 0u;
        }
    }
}

extern "C" void kernel_launch(void* const* d_in, const int* in_sizes, int n_in,
                              void* d_out, int out_size)
{
    const float* pred = (const float*)d_in[0];
    const float* tru  = (const float*)d_in[1];
    const float* mask = (const float*)d_in[2];
    float* out = (float*)d_out;

    fape_kernel<<<GRID, TPB>>>(pred, tru, mask, out);
}

// round 14
// speedup vs baseline: 1.4673x; 1.4673x over previous
#include <cuda_runtime.h>

#define BATCH   64
#define NPTS    4096
#define CHUNKS  2
#define NFRAMES 100
#define FSPLIT  4
#define FPER    (NFRAMES / FSPLIT)   // 25 frames per CTA (compile-time!)
#define TPB     256
#define KPT     8   // NPTS / (CHUNKS*TPB)
#define GRID    (BATCH * CHUNKS * FSPLIT)   // 512

__device__ double g_sum;
__device__ double g_msum;
__device__ unsigned int g_count;

__device__ __forceinline__ float sqrt_approx(float x) {
    float r;
    asm("sqrt.approx.f32 %0, %1;" : "=f"(r) : "f"(x));
    return r;
}
// Last FFMA of the dot-chain carries .sat: clamps s' to [0,1].
// With e' = 0.1*e, saturate(s') == clamp(d^2,0,100)/100, so
// sqrt(sat) == min(d,10)/10 exactly (clamp + loss-unit fused, zero alu ops).
__device__ __forceinline__ float fma_sat(float a, float b, float c) {
    float r;
    asm("fma.rn.sat.f32 %0, %1, %2, %3;" : "=f"(r) : "f"(a), "f"(b), "f"(c));
    return r;
}

__global__ void __launch_bounds__(TPB) fape_kernel(
    const float* __restrict__ pred, const float* __restrict__ tru,
    const float* __restrict__ mask, float* __restrict__ out)
{
    // Frame constants (prescaled by 0.1) for this CTA's 25-frame slice:
    //   sf[f] = (-2*e'_fx, -2*e'_fy, -2*e'_fz, ||e'_f||^2)
    __shared__ float4 sf[FPER];
    __shared__ float wsum[TPB / 32], wm[TPB / 32];

    const int b     = blockIdx.x >> 3;
    const int chunk = (blockIdx.x >> 2) & 1;
    const int fh    = blockIdx.x & 3;
    const int tid   = threadIdx.x;

    const float* pb = pred + (size_t)b * NPTS * 3;
    const float* tb = tru  + (size_t)b * NPTS * 3;
    const float* mb = mask + (size_t)b * NPTS;

    if (tid < FPER) {
        int f = fh * FPER + tid;
        float ex = 0.1f * (pb[3 * f + 0] - tb[3 * f + 0]);
        float ey = 0.1f * (pb[3 * f + 1] - tb[3 * f + 1]);
        float ez = 0.1f * (pb[3 * f + 2] - tb[3 * f + 2]);
        float nf = fmaf(ex, ex, fmaf(ey, ey, ez * ez));
        sf[tid] = make_float4(-2.f * ex, -2.f * ey, -2.f * ez, nf);
    }
    __syncthreads();

    // Eight k-points per thread (independent chains -> ILP), prescaled by 0.1.
    // Mask loaded in the prologue so the epilogue never stalls on fresh LDG.
    const int kbase = chunk * (TPB * KPT) + tid;
    float ex[KPT], ey[KPT], ez[KPT], nn[KPT], acc[KPT], mm[KPT];
#pragma unroll
    for (int j = 0; j < KPT; ++j) {
        int k = kbase + j * TPB;
        ex[j] = 0.1f * (pb[3 * k + 0] - tb[3 * k + 0]);
        ey[j] = 0.1f * (pb[3 * k + 1] - tb[3 * k + 1]);
        ez[j] = 0.1f * (pb[3 * k + 2] - tb[3 * k + 2]);
        nn[j] = fmaf(ex[j], ex[j], fmaf(ey[j], ey[j], ez[j] * ez[j]));
        acc[j] = 0.f;
        mm[j] = mb[k];
    }

    // FULL unroll: compile-time 25 iterations, no loop-carried branch/IADD,
    // lets ptxas front-batch the LDS.128s and interleave all MUFU chains.
#pragma unroll
    for (int f = 0; f < FPER; ++f) {
        float4 F = sf[f];
#pragma unroll
        for (int j = 0; j < KPT; ++j) {
            // s' = sat( n'_k + n'_f + e'_k . (-2 e'_f) ) in [0,1]
            float s = fma_sat(ex[j], F.x,
                              fmaf(ey[j], F.y,
                                   fmaf(ez[j], F.z, nn[j] + F.w)));
            acc[j] += sqrt_approx(s);   // == min(d,10)/10
        }
    }

    float tsum = 0.f, msum = 0.f;
#pragma unroll
    for (int j = 0; j < KPT; ++j) {
        tsum = fmaf(mm[j], acc[j], tsum);
        msum += mm[j];
    }
    // mask sum counted once (frame-split duplicates k-coverage): only fh==0 counts
    if (fh != 0) msum = 0.f;

    // warp reduce
#pragma unroll
    for (int off = 16; off; off >>= 1) {
        tsum += __shfl_down_sync(0xffffffffu, tsum, off);
        msum += __shfl_down_sync(0xffffffffu, msum, off);
    }
    int wid = tid >> 5, lane = tid & 31;
    if (lane == 0) { wsum[wid] = tsum; wm[wid] = msum; }
    __syncthreads();

    if (wid == 0 && lane == 0) {
        float ts = 0.f, ms = 0.f;
#pragma unroll
        for (int w = 0; w < TPB / 32; ++w) { ts += wsum[w]; ms += wm[w]; }
        atomicAdd(&g_sum, (double)ts);
        atomicAdd(&g_msum, (double)ms);
        __threadfence();
        unsigned int done = atomicAdd(&g_count, 1u);
        if (done == GRID - 1) {
            // last CTA: finalize and reset scratch for next graph replay
            // per-pair terms already include the /10 loss unit (prescale form)
            double s = atomicAdd(&g_sum, 0.0);
            double m = atomicAdd(&g_msum, 0.0);
            out[0] = (float)(s / (m + 1e-8));
            g_sum = 0.0;
            g_msum = 0.0;
            g_count = 0u;
        }
    }
}

extern "C" void kernel_launch(void* const* d_in, const int* in_sizes, int n_in,
                              void* d_out, int out_size)
{
    const float* pred = (const float*)d_in[0];
    const float* tru  = (const float*)d_in[1];
    const float* mask = (const float*)d_in[2];
    float* out = (float*)d_out;

    fape_kernel<<<GRID, TPB>>>(pred, tru, mask, out);
}

// round 15
// speedup vs baseline: 1.4896x; 1.0152x over previous
#include <cuda_runtime.h>

#define BATCH   64
#define NPTS    4096
#define CHUNKS  2
#define NFRAMES 100
#define FSPLIT  4
#define FPER    (NFRAMES / FSPLIT)   // 25 frames per CTA
#define TPB     256
#define KPT     8   // NPTS / (CHUNKS*TPB)
#define NEWTON_J 6  // chains j >= NEWTON_J use fma-pipe Newton sqrt (2 of 8 = 25%)
#define GRID    (BATCH * CHUNKS * FSPLIT)   // 512

__device__ double g_sum;
__device__ double g_msum;
__device__ unsigned int g_count;

__device__ __forceinline__ float sqrt_approx(float x) {
    float r;
    asm("sqrt.approx.f32 %0, %1;" : "=f"(r) : "f"(x));
    return r;
}
// Last FFMA of the dot-chain carries .sat: clamps s' to [0,1].
// With e' = 0.1*e, saturate(s') == clamp(d^2,0,100)/100, so
// sqrt(sat) == min(d,10)/10 exactly (clamp + loss-unit fused, zero alu ops).
__device__ __forceinline__ float fma_sat(float a, float b, float c) {
    float r;
    asm("fma.rn.sat.f32 %0, %1, %2, %3;" : "=f"(r) : "f"(a), "f"(b), "f"(c));
    return r;
}
// fma-pipe sqrt: bit-hack rsqrt seed + 2 Newton iters. x in [0,1] (saturated).
// rel err ~1e-5. x==0 -> a=0 propagates -> returns exactly 0 (no inf/NaN path).
// Cost: 2 alu (SHF+IADD) + 8 fma ops; relieves the MUFU pipe.
__device__ __forceinline__ float sqrt_newton(float x) {
    int i = __float_as_int(x);
    i = 0x5f3759df - (i >> 1);
    float y = __int_as_float(i);
    float a = x * y;                        // a = x*y0
    float b = fmaf(-0.5f, a * y, 1.5f);     // 1.5 - 0.5*x*y0^2
    y = y * b;                              // y1
    a = x * y;                              // a = x*y1
    b = fmaf(-0.5f, a * y, 1.5f);           // 1.5 - 0.5*x*y1^2
    return a * b;                           // x*y2 = sqrt(x)
}

__global__ void __launch_bounds__(TPB) fape_kernel(
    const float* __restrict__ pred, const float* __restrict__ tru,
    const float* __restrict__ mask, float* __restrict__ out)
{
    // Frame constants (prescaled by 0.1) for this CTA's 25-frame slice:
    //   sf[f] = (-2*e'_fx, -2*e'_fy, -2*e'_fz, ||e'_f||^2)
    __shared__ float4 sf[FPER];
    __shared__ float wsum[TPB / 32], wm[TPB / 32];

    const int b     = blockIdx.x >> 3;
    const int chunk = (blockIdx.x >> 2) & 1;
    const int fh    = blockIdx.x & 3;
    const int tid   = threadIdx.x;

    const float* pb = pred + (size_t)b * NPTS * 3;
    const float* tb = tru  + (size_t)b * NPTS * 3;
    const float* mb = mask + (size_t)b * NPTS;

    if (tid < FPER) {
        int f = fh * FPER + tid;
        float ex = 0.1f * (pb[3 * f + 0] - tb[3 * f + 0]);
        float ey = 0.1f * (pb[3 * f + 1] - tb[3 * f + 1]);
        float ez = 0.1f * (pb[3 * f + 2] - tb[3 * f + 2]);
        float nf = fmaf(ex, ex, fmaf(ey, ey, ez * ez));
        sf[tid] = make_float4(-2.f * ex, -2.f * ey, -2.f * ez, nf);
    }
    __syncthreads();

    // Eight k-points per thread (independent chains -> ILP), prescaled by 0.1
    const int kbase = chunk * (TPB * KPT) + tid;
    float ex[KPT], ey[KPT], ez[KPT], nn[KPT], acc[KPT];
#pragma unroll
    for (int j = 0; j < KPT; ++j) {
        int k = kbase + j * TPB;
        ex[j] = 0.1f * (pb[3 * k + 0] - tb[3 * k + 0]);
        ey[j] = 0.1f * (pb[3 * k + 1] - tb[3 * k + 1]);
        ez[j] = 0.1f * (pb[3 * k + 2] - tb[3 * k + 2]);
        nn[j] = fmaf(ex[j], ex[j], fmaf(ey[j], ey[j], ez[j] * ez[j]));
        acc[j] = 0.f;
    }

#pragma unroll 5
    for (int f = 0; f < FPER; ++f) {
        float4 F = sf[f];
#pragma unroll
        for (int j = 0; j < KPT; ++j) {
            // s' = sat( n'_k + n'_f + e'_k . (-2 e'_f) ) in [0,1]
            float s = fma_sat(ex[j], F.x,
                              fmaf(ey[j], F.y,
                                   fmaf(ez[j], F.z, nn[j] + F.w)));
            // split sqrt across pipes: 6 chains on MUFU, 2 on fma-pipe Newton
            if (j < NEWTON_J)
                acc[j] += sqrt_approx(s);    // == min(d,10)/10
            else
                acc[j] += sqrt_newton(s);
        }
    }

    float tsum = 0.f, msum = 0.f;
#pragma unroll
    for (int j = 0; j < KPT; ++j) {
        float m = mb[kbase + j * TPB];
        tsum = fmaf(m, acc[j], tsum);
        msum += m;
    }
    // mask sum counted once (frame-split duplicates k-coverage): only fh==0 counts
    if (fh != 0) msum = 0.f;

    // warp reduce
#pragma unroll
    for (int off = 16; off; off >>= 1) {
        tsum += __shfl_down_sync(0xffffffffu, tsum, off);
        msum += __shfl_down_sync(0xffffffffu, msum, off);
    }
    int wid = tid >> 5, lane = tid & 31;
    if (lane == 0) { wsum[wid] = tsum; wm[wid] = msum; }
    __syncthreads();

    if (wid == 0 && lane == 0) {
        float ts = 0.f, ms = 0.f;
#pragma unroll
        for (int w = 0; w < TPB / 32; ++w) { ts += wsum[w]; ms += wm[w]; }
        atomicAdd(&g_sum, (double)ts);
        atomicAdd(&g_msum, (double)ms);
        __threadfence();
        unsigned int done = atomicAdd(&g_count, 1u);
        if (done == GRID - 1) {
            // last CTA: finalize and reset scratch for next graph replay
            // per-pair terms already include the /10 loss unit (prescale form)
            double s = atomicAdd(&g_sum, 0.0);
            double m = atomicAdd(&g_msum, 0.0);
            out[0] = (float)(s / (m + 1e-8));
            g_sum = 0.0;
            g_msum = 0.0;
            g_count = 0u;
        }
    }
}

extern "C" void kernel_launch(void* const* d_in, const int* in_sizes, int n_in,
                              void* d_out, int out_size)
{
    const float* pred = (const float*)d_in[0];
    const float* tru  = (const float*)d_in[1];
    const float* mask = (const float*)d_in[2];
    float* out = (float*)d_out;

    fape_kernel<<<GRID, TPB>>>(pred, tru, mask, out);
}

// round 16
// speedup vs baseline: 1.5184x; 1.0193x over previous
#include <cuda_runtime.h>

#define BATCH   64
#define NPTS    4096
#define CHUNKS  2
#define NFRAMES 100
#define FSPLIT  4
#define FPER    (NFRAMES / FSPLIT)   // 25 frames per CTA
#define TPB     256
#define KPT     8   // NPTS / (CHUNKS*TPB)
#define GRID    (BATCH * CHUNKS * FSPLIT)   // 512

__device__ double g_sum;
__device__ double g_msum;
__device__ unsigned int g_count;

// Guaranteed single MUFU.RSQ (no zero-fixup emulation).
__device__ __forceinline__ float rsqrt_approx(float x) {
    float r;
    asm("rsqrt.approx.f32 %0, %1;" : "=f"(r) : "f"(x));
    return r;
}
// Last FFMA of the dot-chain carries .sat: clamps s' to [0,1].
// With e' = 0.1*e, saturate(s') == clamp(d^2,0,100)/100, so
// sqrt(sat) == min(d,10)/10 exactly (clamp + loss-unit fused).
__device__ __forceinline__ float fma_sat(float a, float b, float c) {
    float r;
    asm("fma.rn.sat.f32 %0, %1, %2, %3;" : "=f"(r) : "f"(a), "f"(b), "f"(c));
    return r;
}

__global__ void __launch_bounds__(TPB) fape_kernel(
    const float* __restrict__ pred, const float* __restrict__ tru,
    const float* __restrict__ mask, float* __restrict__ out)
{
    // Frame constants (prescaled by 0.1) for this CTA's 25-frame slice:
    //   sf[f] = (-2*e'_fx, -2*e'_fy, -2*e'_fz, ||e'_f||^2)
    __shared__ float4 sf[FPER];
    __shared__ float wsum[TPB / 32], wm[TPB / 32];

    const int b     = blockIdx.x >> 3;
    const int chunk = (blockIdx.x >> 2) & 1;
    const int fh    = blockIdx.x & 3;
    const int tid   = threadIdx.x;

    const float* pb = pred + (size_t)b * NPTS * 3;
    const float* tb = tru  + (size_t)b * NPTS * 3;
    const float* mb = mask + (size_t)b * NPTS;

    if (tid < FPER) {
        int f = fh * FPER + tid;
        float ex = 0.1f * (pb[3 * f + 0] - tb[3 * f + 0]);
        float ey = 0.1f * (pb[3 * f + 1] - tb[3 * f + 1]);
        float ez = 0.1f * (pb[3 * f + 2] - tb[3 * f + 2]);
        float nf = fmaf(ex, ex, fmaf(ey, ey, ez * ez));
        sf[tid] = make_float4(-2.f * ex, -2.f * ey, -2.f * ez, nf);
    }
    __syncthreads();

    // Eight k-points per thread (independent chains -> ILP), prescaled by 0.1
    const int kbase = chunk * (TPB * KPT) + tid;
    float ex[KPT], ey[KPT], ez[KPT], nn[KPT], acc[KPT];
#pragma unroll
    for (int j = 0; j < KPT; ++j) {
        int k = kbase + j * TPB;
        ex[j] = 0.1f * (pb[3 * k + 0] - tb[3 * k + 0]);
        ey[j] = 0.1f * (pb[3 * k + 1] - tb[3 * k + 1]);
        ez[j] = 0.1f * (pb[3 * k + 2] - tb[3 * k + 2]);
        nn[j] = fmaf(ex[j], ex[j], fmaf(ey[j], ey[j], ez[j] * ez[j]));
        acc[j] = 0.f;
    }

#pragma unroll 5
    for (int f = 0; f < FPER; ++f) {
        float4 F = sf[f];
#pragma unroll
        for (int j = 0; j < KPT; ++j) {
            // s' = sat( n'_k + n'_f + e'_k . (-2 e'_f) ) in [0,1]
            float s = fma_sat(ex[j], F.x,
                              fmaf(ey[j], F.y,
                                   fmaf(ez[j], F.z, nn[j] + F.w)));
            // sqrt(s) == s * rsqrt(s + tiny): single MUFU.RSQ, no predicated
            // zero-fixup (s==0 -> 0 * finite = 0). err <= 3e-10 absolute.
            float r = rsqrt_approx(s + 1e-18f);
            acc[j] = fmaf(s, r, acc[j]);   // += min(d,10)/10
        }
    }

    float tsum = 0.f, msum = 0.f;
#pragma unroll
    for (int j = 0; j < KPT; ++j) {
        float m = mb[kbase + j * TPB];
        tsum = fmaf(m, acc[j], tsum);
        msum += m;
    }
    // mask sum counted once (frame-split duplicates k-coverage): only fh==0 counts
    if (fh != 0) msum = 0.f;

    // warp reduce
#pragma unroll
    for (int off = 16; off; off >>= 1) {
        tsum += __shfl_down_sync(0xffffffffu, tsum, off);
        msum += __shfl_down_sync(0xffffffffu, msum, off);
    }
    int wid = tid >> 5, lane = tid & 31;
    if (lane == 0) { wsum[wid] = tsum; wm[wid] = msum; }
    __syncthreads();

    if (wid == 0 && lane == 0) {
        float ts = 0.f, ms = 0.f;
#pragma unroll
        for (int w = 0; w < TPB / 32; ++w) { ts += wsum[w]; ms += wm[w]; }
        atomicAdd(&g_sum, (double)ts);
        atomicAdd(&g_msum, (double)ms);
        __threadfence();
        unsigned int done = atomicAdd(&g_count, 1u);
        if (done == GRID - 1) {
            // last CTA: finalize and reset scratch for next graph replay
            // per-pair terms already include the /10 loss unit (prescale form)
            double s = atomicAdd(&g_sum, 0.0);
            double m = atomicAdd(&g_msum, 0.0);
            out[0] = (float)(s / (m + 1e-8));
            g_sum = 0.0;
            g_msum = 0.0;
            g_count = 0u;
        }
    }
}

extern "C" void kernel_launch(void* const* d_in, const int* in_sizes, int n_in,
                              void* d_out, int out_size)
{
    const float* pred = (const float*)d_in[0];
    const float* tru  = (const float*)d_in[1];
    const float* mask = (const float*)d_in[2];
    float* out = (float*)d_out;

    fape_kernel<<<GRID, TPB>>>(pred, tru, mask, out);
}

// round 17
// speedup vs baseline: 1.6918x; 1.1142x over previous
#include <cuda_runtime.h>

#define BATCH   64
#define NPTS    4096
#define CHUNKS  4
#define NFRAMES 100
#define FSPLIT  4
#define FPER    (NFRAMES / FSPLIT)   // 25 frames per CTA
#define TPB     256
#define KPT     4   // NPTS / (CHUNKS*TPB)
#define GRID    (BATCH * CHUNKS * FSPLIT)   // 1024 -> ~7 CTAs/SM at regs~40

__device__ double g_sum;
__device__ double g_msum;
__device__ unsigned int g_count;

// Guaranteed single MUFU.RSQ (no zero-fixup emulation).
__device__ __forceinline__ float rsqrt_approx(float x) {
    float r;
    asm("rsqrt.approx.f32 %0, %1;" : "=f"(r) : "f"(x));
    return r;
}
// Last FFMA of the dot-chain carries .sat: clamps s' to [0,1].
// With e' = 0.1*e, saturate(s') == clamp(d^2,0,100)/100, so
// sqrt(sat) == min(d,10)/10 exactly (clamp + loss-unit fused).
__device__ __forceinline__ float fma_sat(float a, float b, float c) {
    float r;
    asm("fma.rn.sat.f32 %0, %1, %2, %3;" : "=f"(r) : "f"(a), "f"(b), "f"(c));
    return r;
}

__global__ void __launch_bounds__(TPB) fape_kernel(
    const float* __restrict__ pred, const float* __restrict__ tru,
    const float* __restrict__ mask, float* __restrict__ out)
{
    // Frame constants (prescaled by 0.1) for this CTA's 25-frame slice:
    //   sf[f] = (-2*e'_fx, -2*e'_fy, -2*e'_fz, ||e'_f||^2)
    __shared__ float4 sf[FPER];
    __shared__ float wsum[TPB / 32], wm[TPB / 32];

    const int b     = blockIdx.x >> 4;
    const int chunk = (blockIdx.x >> 2) & 3;
    const int fh    = blockIdx.x & 3;
    const int tid   = threadIdx.x;

    const float* pb = pred + (size_t)b * NPTS * 3;
    const float* tb = tru  + (size_t)b * NPTS * 3;
    const float* mb = mask + (size_t)b * NPTS;

    if (tid < FPER) {
        int f = fh * FPER + tid;
        float ex = 0.1f * (pb[3 * f + 0] - tb[3 * f + 0]);
        float ey = 0.1f * (pb[3 * f + 1] - tb[3 * f + 1]);
        float ez = 0.1f * (pb[3 * f + 2] - tb[3 * f + 2]);
        float nf = fmaf(ex, ex, fmaf(ey, ey, ez * ez));
        sf[tid] = make_float4(-2.f * ex, -2.f * ey, -2.f * ez, nf);
    }
    __syncthreads();

    // Four k-points per thread (independent chains -> ILP), prescaled by 0.1
    const int kbase = chunk * (TPB * KPT) + tid;
    float ex[KPT], ey[KPT], ez[KPT], nn[KPT], acc[KPT];
#pragma unroll
    for (int j = 0; j < KPT; ++j) {
        int k = kbase + j * TPB;
        ex[j] = 0.1f * (pb[3 * k + 0] - tb[3 * k + 0]);
        ey[j] = 0.1f * (pb[3 * k + 1] - tb[3 * k + 1]);
        ez[j] = 0.1f * (pb[3 * k + 2] - tb[3 * k + 2]);
        nn[j] = fmaf(ex[j], ex[j], fmaf(ey[j], ey[j], ez[j] * ez[j]));
        acc[j] = 0.f;
    }

#pragma unroll 5
    for (int f = 0; f < FPER; ++f) {
        float4 F = sf[f];
#pragma unroll
        for (int j = 0; j < KPT; ++j) {
            // s' = sat( n'_k + n'_f + e'_k . (-2 e'_f) ) in [0,1]
            float s = fma_sat(ex[j], F.x,
                              fmaf(ey[j], F.y,
                                   fmaf(ez[j], F.z, nn[j] + F.w)));
            // sqrt(s) == s * rsqrt(max(s,tiny)): single MUFU.RSQ; the max is an
            // FMNMX on the (idle) alu pipe, not an fma-slot FADD. s==0 -> 0.
            float r = rsqrt_approx(fmaxf(s, 1e-18f));
            acc[j] = fmaf(s, r, acc[j]);   // += min(d,10)/10
        }
    }

    float tsum = 0.f, msum = 0.f;
#pragma unroll
    for (int j = 0; j < KPT; ++j) {
        float m = mb[kbase + j * TPB];
        tsum = fmaf(m, acc[j], tsum);
        msum += m;
    }
    // mask sum counted once (frame-split duplicates k-coverage): only fh==0 counts
    if (fh != 0) msum = 0.f;

    // warp reduce
#pragma unroll
    for (int off = 16; off; off >>= 1) {
        tsum += __shfl_down_sync(0xffffffffu, tsum, off);
        msum += __shfl_down_sync(0xffffffffu, msum, off);
    }
    int wid = tid >> 5, lane = tid & 31;
    if (lane == 0) { wsum[wid] = tsum; wm[wid] = msum; }
    __syncthreads();

    if (wid == 0 && lane == 0) {
        float ts = 0.f, ms = 0.f;
#pragma unroll
        for (int w = 0; w < TPB / 32; ++w) { ts += wsum[w]; ms += wm[w]; }
        atomicAdd(&g_sum, (double)ts);
        atomicAdd(&g_msum, (double)ms);
        __threadfence();
        unsigned int done = atomicAdd(&g_count, 1u);
        if (done == GRID - 1) {
            // last CTA: finalize and reset scratch for next graph replay
            // per-pair terms already include the /10 loss unit (prescale form)
            double s = atomicAdd(&g_sum, 0.0);
            double m = atomicAdd(&g_msum, 0.0);
            out[0] = (float)(s / (m + 1e-8));
            g_sum = 0.0;
            g_msum = 0.0;
            g_count = 0u;
        }
    }
}

extern "C" void kernel_launch(void* const* d_in, const int* in_sizes, int n_in,
                              void* d_out, int out_size)
{
    const float* pred = (const float*)d_in[0];
    const float* tru  = (const float*)d_in[1];
    const float* mask = (const float*)d_in[2];
    float* out = (float*)d_out;

    fape_kernel<<<GRID, TPB>>>(pred, tru, mask, out);
}